// round 1
// baseline (speedup 1.0000x reference)
#include <cuda_runtime.h>
#include <math.h>

// BucketingBBoxCoder decode, GB300 sm_103a.
// Layout: one thread per proposal. cls_preds and offset_preds are both
// 28 contiguous floats per proposal (4 edges x 7 buckets) -> 7x float4 each.

#define BB  8
#define NN  131072
#define TOTAL (BB * NN)          // 1,048,576 proposals
#define SIDEB 7
#define SCALE_F 3.0f
#define INV_NB (1.0f / 14.0f)    // 1 / NUM_BUCKETS
#define W_CLAMP 1332.0f          // W - 1
#define H_CLAMP 799.0f           // H - 1

__global__ __launch_bounds__(256)
void bucketing_bbox_kernel(const float4* __restrict__ proposals,   // [TOTAL] float4
                           const float4* __restrict__ cls4,        // [TOTAL*7] float4
                           const float4* __restrict__ off4,        // [TOTAL*7] float4
                           float4* __restrict__ out_bbox,          // [TOTAL] float4
                           float* __restrict__ out_conf)           // [TOTAL]
{
    const int p = blockIdx.x * blockDim.x + threadIdx.x;
    if (p >= TOTAL) return;

    // ---- loads ----
    const float4 pr = proposals[p];

    float c[28], o[28];
    const size_t base = (size_t)p * 7;
#pragma unroll
    for (int k = 0; k < 7; k++) {
        float4 v = cls4[base + k];
        c[4*k+0] = v.x; c[4*k+1] = v.y; c[4*k+2] = v.z; c[4*k+3] = v.w;
        float4 w = off4[base + k];
        o[4*k+0] = w.x; o[4*k+1] = w.y; o[4*k+2] = w.z; o[4*k+3] = w.w;
    }

    // ---- geometry ----
    const float cx = (pr.x + pr.z) * 0.5f;
    const float cy = (pr.y + pr.w) * 0.5f;
    const float pw = (pr.z - pr.x) * SCALE_F;
    const float ph = (pr.w - pr.y) * SCALE_F;
    const float px1 = cx - 0.5f * pw;
    const float px2 = cx + 0.5f * pw;
    const float py1 = cy - 0.5f * ph;
    const float py2 = cy + 0.5f * ph;
    const float bw = pw * INV_NB;
    const float bh = ph * INV_NB;

    // Per-edge parameters: e=0 left(x1), e=1 right(x2), e=2 top(y1), e=3 down(y2)
    const float edge_base[4] = { px1, px2, py1, py2 };
    const float edge_sign[4] = { 1.0f, -1.0f, 1.0f, -1.0f };
    const float edge_bsz [4] = { bw, bw, bh, bh };
    const float edge_hi  [4] = { W_CLAMP, W_CLAMP, H_CLAMP, H_CLAMP };

    float coord[4];
    float conf_sum = 0.0f;

#pragma unroll
    for (int e = 0; e < 4; e++) {
        const float* ce = &c[e * 7];

        // top-1 / top-2 over 7 logits, lower-index-first on ties
        float m1 = ce[0]; int i1 = 0;
        float m2 = -INFINITY; int i2 = 0;
#pragma unroll
        for (int s = 1; s < SIDEB; s++) {
            float v = ce[s];
            if (v > m1)      { m2 = m1; i2 = i1; m1 = v; i1 = s; }
            else if (v > m2) { m2 = v; i2 = s; }
        }

        // softmax top values: t1 = exp(0)/sum, t2 = exp(m2-m1)/sum
        float sum = 0.0f;
#pragma unroll
        for (int s = 0; s < SIDEB; s++)
            sum += expf(ce[s] - m1);
        const float inv_sum = 1.0f / sum;
        const float t1 = inv_sum;
        const float t2 = expf(m2 - m1) * inv_sum;

        int d = i1 - i2;
        conf_sum += t1 + t2 * (fabsf((float)d) - 1.0f);

        // bucket + offset refinement
        const float offv = o[e * 7 + i1];
        float cval = edge_base[e]
                   + edge_sign[e] * (0.5f + (float)i1) * edge_bsz[e]
                   - offv * edge_bsz[e];
        cval = fminf(fmaxf(cval, 0.0f), edge_hi[e]);
        coord[e] = cval;
    }

    // bboxes stacked as [x1, y1, x2, y2]
    float4 bb;
    bb.x = coord[0];  // x1 (left)
    bb.y = coord[2];  // y1 (top)
    bb.z = coord[1];  // x2 (right)
    bb.w = coord[3];  // y2 (down)
    out_bbox[p] = bb;

    out_conf[p] = conf_sum * 0.25f;
}

extern "C" void kernel_launch(void* const* d_in, const int* in_sizes, int n_in,
                              void* d_out, int out_size)
{
    const float4* proposals = (const float4*)d_in[0];
    const float4* cls4      = (const float4*)d_in[1];
    const float4* off4      = (const float4*)d_in[2];

    float4* out_bbox = (float4*)d_out;                       // TOTAL float4
    float*  out_conf = (float*)d_out + (size_t)TOTAL * 4;    // TOTAL floats

    const int threads = 256;
    const int blocks  = (TOTAL + threads - 1) / threads;
    bucketing_bbox_kernel<<<blocks, threads>>>(proposals, cls4, off4,
                                               out_bbox, out_conf);
}

// round 2
// speedup vs baseline: 1.1826x; 1.1826x over previous
#include <cuda_runtime.h>
#include <math.h>

// BucketingBBoxCoder decode, GB300 sm_103a. Round 2:
// - No runtime-indexed register arrays (R1 had o[e*7+i1] -> local memory).
//   Offset selection is folded into the top-k scan via predicated updates,
//   so everything stays in registers with static indices after unroll.

#define BB  8
#define NN  131072
#define TOTAL (BB * NN)          // 1,048,576 proposals
#define SCALE_F 3.0f
#define INV_NB (1.0f / 14.0f)    // 1 / NUM_BUCKETS
#define W_CLAMP 1332.0f          // W - 1
#define H_CLAMP 799.0f           // H - 1

__global__ __launch_bounds__(256)
void bucketing_bbox_kernel(const float4* __restrict__ proposals,   // [TOTAL] float4
                           const float4* __restrict__ cls4,        // [TOTAL*7] float4
                           const float4* __restrict__ off4,        // [TOTAL*7] float4
                           float4* __restrict__ out_bbox,          // [TOTAL] float4
                           float* __restrict__ out_conf)           // [TOTAL]
{
    const int p = blockIdx.x * blockDim.x + threadIdx.x;
    if (p >= TOTAL) return;

    // ---- front-batched loads (MLP) ----
    const float4 pr = proposals[p];

    const size_t base = (size_t)p * 7;
    float c[28], o[28];
#pragma unroll
    for (int k = 0; k < 7; k++) {
        float4 v = cls4[base + k];
        c[4*k+0] = v.x; c[4*k+1] = v.y; c[4*k+2] = v.z; c[4*k+3] = v.w;
        float4 w = off4[base + k];
        o[4*k+0] = w.x; o[4*k+1] = w.y; o[4*k+2] = w.z; o[4*k+3] = w.w;
    }

    // ---- geometry ----
    const float cx = (pr.x + pr.z) * 0.5f;
    const float cy = (pr.y + pr.w) * 0.5f;
    const float pw = (pr.z - pr.x) * SCALE_F;
    const float ph = (pr.w - pr.y) * SCALE_F;
    const float px1 = cx - 0.5f * pw;
    const float px2 = cx + 0.5f * pw;
    const float py1 = cy - 0.5f * ph;
    const float py2 = cy + 0.5f * ph;
    const float bw = pw * INV_NB;
    const float bh = ph * INV_NB;

    const float edge_base[4] = { px1, px2, py1, py2 };
    const float edge_sign[4] = { 1.0f, -1.0f, 1.0f, -1.0f };
    const float edge_bsz [4] = { bw, bw, bh, bh };
    const float edge_hi  [4] = { W_CLAMP, W_CLAMP, H_CLAMP, H_CLAMP };

    float coord[4];
    float conf_sum = 0.0f;

#pragma unroll
    for (int e = 0; e < 4; e++) {
        // top-1 / top-2 over 7 logits with lower-index-first tie-break;
        // offset value captured in the SAME predicated update -> no dynamic index.
        float m1 = c[e*7 + 0];
        float offv = o[e*7 + 0];
        int   i1 = 0;
        float m2 = -INFINITY;
        int   i2 = 0;
#pragma unroll
        for (int s = 1; s < 7; s++) {
            const float v  = c[e*7 + s];
            const float ov = o[e*7 + s];
            if (v > m1) {
                m2 = m1; i2 = i1;
                m1 = v;  i1 = s;  offv = ov;
            } else if (v > m2) {
                m2 = v;  i2 = s;
            }
        }

        // softmax top values without a separate max pass:
        // t1 = 1/sum(exp(c-m1)), t2 = exp(m2-m1)*t1
        float sum = 0.0f;
#pragma unroll
        for (int s = 0; s < 7; s++)
            sum += __expf(c[e*7 + s] - m1);
        const float t1 = 1.0f / sum;
        const float t2 = __expf(m2 - m1) * t1;

        conf_sum += t1 + t2 * (fabsf((float)(i1 - i2)) - 1.0f);

        float cval = edge_base[e]
                   + edge_sign[e] * (0.5f + (float)i1) * edge_bsz[e]
                   - offv * edge_bsz[e];
        coord[e] = fminf(fmaxf(cval, 0.0f), edge_hi[e]);
    }

    float4 bb;
    bb.x = coord[0];  // x1
    bb.y = coord[2];  // y1
    bb.z = coord[1];  // x2
    bb.w = coord[3];  // y2
    out_bbox[p] = bb;
    out_conf[p] = conf_sum * 0.25f;
}

extern "C" void kernel_launch(void* const* d_in, const int* in_sizes, int n_in,
                              void* d_out, int out_size)
{
    const float4* proposals = (const float4*)d_in[0];
    const float4* cls4      = (const float4*)d_in[1];
    const float4* off4      = (const float4*)d_in[2];

    float4* out_bbox = (float4*)d_out;                       // TOTAL float4
    float*  out_conf = (float*)d_out + (size_t)TOTAL * 4;    // TOTAL floats

    const int threads = 256;
    const int blocks  = (TOTAL + threads - 1) / threads;
    bucketing_bbox_kernel<<<blocks, threads>>>(proposals, cls4, off4,
                                               out_bbox, out_conf);
}